// round 2
// baseline (speedup 1.0000x reference)
#include <cuda_runtime.h>
#include <cstdint>

#define N 8192

// ---------------- device scratch (no allocations allowed) ----------------
__device__ float g_xmT[64 * N];   // built query features, transposed [64][N]
__device__ float g_xvT[96 * N];   // [96][N]
__device__ float g_XmT[64 * N];   // X_mean transposed
__device__ float g_XvT[96 * N];   // X_var transposed
__device__ float g_qn_mean[N];    // ||x_mean row||^2
__device__ float g_qn_var[N];
__device__ float g_Xn_mean[N];    // ||X_mean row||^2
__device__ float g_Xn_var[N];
__device__ float g_Lmean[N * 32]; // Lambda_mean
__device__ float g_Lvar[N * 32];  // Lambda_var

// ---------------- zero Lambda accumulators ----------------
__global__ void zero_L_kernel() {
    int i = blockIdx.x * blockDim.x + threadIdx.x;
    const int total = N * 32;
    for (; i < total; i += gridDim.x * blockDim.x) {
        g_Lmean[i] = 0.0f;
        g_Lvar[i]  = 0.0f;
    }
}

// ---------------- build query features (transposed) + norms + seed output ----------------
// x_mean = [x_mu, y_mean+y_var]            (64)
// x_var  = [x_mu, 0.01*flip(y_eta), y_mean+y_var] (96)
// out    = y_mean + y_var   (z terms added later via atomicAdd)
__global__ __launch_bounds__(256) void build_queries_kernel(
    const float* __restrict__ x_mu, const float* __restrict__ y_eta,
    const float* __restrict__ y_mean, const float* __restrict__ y_var,
    float* __restrict__ out)
{
    __shared__ float sa[32][33];
    __shared__ float se[32][33];
    __shared__ float ss[32][33];
    int q0   = blockIdx.x * 32;
    int tid  = threadIdx.x;
    int lane = tid & 31;
    int w    = tid >> 5;

#pragma unroll
    for (int rr = 0; rr < 4; rr++) {
        int qr = w + rr * 8;
        int q  = q0 + qr;
        float a = x_mu[q * 32 + lane];
        float s = y_mean[q * 32 + lane] + y_var[q * 32 + lane];
        float e = 0.01f * y_eta[(N - 1 - q) * 32 + lane];
        sa[qr][lane] = a;
        se[qr][lane] = e;
        ss[qr][lane] = s;
        out[q * 32 + lane] = s;
        float nm = a * a + s * s;
        float nv = nm + e * e;
#pragma unroll
        for (int o = 16; o > 0; o >>= 1) {
            nm += __shfl_xor_sync(0xffffffffu, nm, o);
            nv += __shfl_xor_sync(0xffffffffu, nv, o);
        }
        if (lane == 0) { g_qn_mean[q] = nm; g_qn_var[q] = nv; }
    }
    __syncthreads();
    // transposed writes: coalesced over q
    for (int idx = tid; idx < 64 * 32; idx += 256) {
        int k = idx >> 5, c = idx & 31;
        float v = (k < 32) ? sa[c][k] : ss[c][k - 32];
        g_xmT[k * N + q0 + c] = v;
    }
    for (int idx = tid; idx < 96 * 32; idx += 256) {
        int k = idx >> 5, c = idx & 31;
        float v = (k < 32) ? sa[c][k] : ((k < 64) ? se[c][k - 32] : ss[c][k - 64]);
        g_xvT[k * N + q0 + c] = v;
    }
}

// ---------------- transpose X + row norms ----------------
template <int D, int V>
__global__ __launch_bounds__(256) void transpose_norm_kernel(const float* __restrict__ X)
{
    float* XT = V ? g_XvT : g_XmT;
    float* n2 = V ? g_Xn_var : g_Xn_mean;
    __shared__ float s[32][D + 1];
    int q0  = blockIdx.x * 32;
    int tid = threadIdx.x;
    for (int idx = tid; idx < 32 * D; idx += 256) {
        int r = idx / D, c = idx - r * D;
        s[r][c] = X[(q0 + r) * D + c];
    }
    __syncthreads();
    if (tid < 32) {
        float acc = 0.0f;
#pragma unroll 8
        for (int k = 0; k < D; k++) { float v = s[tid][k]; acc = fmaf(v, v, acc); }
        n2[q0 + tid] = acc;
    }
    for (int idx = tid; idx < D * 32; idx += 256) {
        int k = idx >> 5, c = idx & 31;
        XT[k * N + q0 + c] = s[c][k];
    }
}

// ---------------- Lambda = kXX_inv @ Z   ([N][N] @ [N][32]) ----------------
// grid (32 row-blocks of 256 rows, 8 k-splits), block 256, thread tile 4 rows x 8 cols
template <int V>
__global__ __launch_bounds__(256) void lambda_gemm_kernel(
    const float* __restrict__ A, const float* __restrict__ B)
{
    float* C = V ? g_Lvar : g_Lmean;
    __shared__ float sA[256][20];
    __shared__ float sB[16][36];
    int tid   = threadIdx.x;
    int r0    = blockIdx.x * 256;
    int kbase = blockIdx.y * (N / 8);
    int tx = tid & 3;        // col group: 8 cols
    int ty = tid >> 2;       // 0..63: rows ty*4..+3

    float acc[4][8];
#pragma unroll
    for (int i = 0; i < 4; i++)
#pragma unroll
        for (int j = 0; j < 8; j++) acc[i][j] = 0.0f;

    for (int kc = kbase; kc < kbase + N / 8; kc += 16) {
#pragma unroll
        for (int i = 0; i < 4; i++) {
            int f   = tid + 256 * i;
            int row = f >> 2;
            int kq  = (f & 3) << 2;
            float4 v = *reinterpret_cast<const float4*>(&A[(size_t)(r0 + row) * N + kc + kq]);
            *reinterpret_cast<float4*>(&sA[row][kq]) = v;
        }
        if (tid < 128) {
            int k = tid >> 3, jq = (tid & 7) << 2;
            *reinterpret_cast<float4*>(&sB[k][jq]) =
                *reinterpret_cast<const float4*>(&B[(kc + k) * 32 + jq]);
        }
        __syncthreads();
#pragma unroll
        for (int k = 0; k < 16; k++) {
            float4 b0 = *reinterpret_cast<const float4*>(&sB[k][tx * 8]);
            float4 b1 = *reinterpret_cast<const float4*>(&sB[k][tx * 8 + 4]);
#pragma unroll
            for (int i = 0; i < 4; i++) {
                float a = sA[ty * 4 + i][k];
                acc[i][0] = fmaf(a, b0.x, acc[i][0]);
                acc[i][1] = fmaf(a, b0.y, acc[i][1]);
                acc[i][2] = fmaf(a, b0.z, acc[i][2]);
                acc[i][3] = fmaf(a, b0.w, acc[i][3]);
                acc[i][4] = fmaf(a, b1.x, acc[i][4]);
                acc[i][5] = fmaf(a, b1.y, acc[i][5]);
                acc[i][6] = fmaf(a, b1.z, acc[i][6]);
                acc[i][7] = fmaf(a, b1.w, acc[i][7]);
            }
        }
        __syncthreads();
    }
#pragma unroll
    for (int i = 0; i < 4; i++)
#pragma unroll
        for (int j = 0; j < 8; j++)
            atomicAdd(&C[(size_t)(r0 + ty * 4 + i) * 32 + tx * 8 + j], acc[i][j]);
}

// ---------------- fused RBF + z gemm ----------------
// z[q][:] += sum_n exp(min(2*dot - ||X_n||^2 - ||x_q||^2, 0)/128) * Lambda[n][:]
// grid (128 q-tiles of 64, 2 n-splits of 4096), block 256
template <int D, int V>
__global__ __launch_bounds__(256) void fused_rbf_kernel(float* __restrict__ out)
{
    const float* XT  = V ? g_XvT     : g_XmT;
    const float* qT  = V ? g_xvT     : g_xmT;
    const float* Xn2 = V ? g_Xn_var  : g_Xn_mean;
    const float* qn2 = V ? g_qn_var  : g_qn_mean;
    const float* Lam = V ? g_Lvar    : g_Lmean;

    extern __shared__ float sm[];
    float* sq  = sm;              // [D][68]
    float* sX  = sq + D * 68;     // [D][68]
    float* sK  = sX + D * 68;     // [64][68]
    float* sL  = sK + 64 * 68;    // [64][36]
    float* sXn = sL + 64 * 36;    // [64]
    float* sqn = sXn + 64;        // [64]

    int tid    = threadIdx.x;
    int q0     = blockIdx.x * 64;
    int n0base = blockIdx.y * (N / 2);

    for (int idx = tid; idx < D * 64; idx += 256) {
        int k = idx >> 6, c = idx & 63;
        sq[k * 68 + c] = qT[k * N + q0 + c];
    }
    if (tid < 64) sqn[tid] = qn2[q0 + tid];

    float z[8];
#pragma unroll
    for (int i = 0; i < 8; i++) z[i] = 0.0f;

    int qs = tid >> 4;   // 0..15 (S-phase q group of 4)
    int ns = tid & 15;   // 0..15 (S-phase n group of 4)
    int qz = tid >> 5;   // 0..7  (z-phase q group of 8)
    int j  = tid & 31;   // z-phase output column

    for (int n0 = n0base; n0 < n0base + N / 2; n0 += 64) {
        __syncthreads();
        for (int idx = tid; idx < D * 64; idx += 256) {
            int k = idx >> 6, c = idx & 63;
            sX[k * 68 + c] = XT[k * N + n0 + c];
        }
        for (int idx = tid; idx < 512; idx += 256) {
            int n = idx >> 3, jq = (idx & 7) << 2;
            *reinterpret_cast<float4*>(&sL[n * 36 + jq]) =
                *reinterpret_cast<const float4*>(&Lam[(n0 + n) * 32 + jq]);
        }
        if (tid < 64) sXn[tid] = Xn2[n0 + tid];
        __syncthreads();

        // S phase: 4x4 dots
        float s[4][4];
#pragma unroll
        for (int i = 0; i < 4; i++)
#pragma unroll
            for (int jj = 0; jj < 4; jj++) s[i][jj] = 0.0f;

#pragma unroll 4
        for (int k = 0; k < D; k++) {
            float4 xa = *reinterpret_cast<const float4*>(&sX[k * 68 + ns * 4]);
            float4 qa = *reinterpret_cast<const float4*>(&sq[k * 68 + qs * 4]);
            float xv[4] = {xa.x, xa.y, xa.z, xa.w};
            float qv[4] = {qa.x, qa.y, qa.z, qa.w};
#pragma unroll
            for (int i = 0; i < 4; i++)
#pragma unroll
                for (int jj = 0; jj < 4; jj++)
                    s[i][jj] = fmaf(xv[i], qv[jj], s[i][jj]);
        }
        // exp + write K tile
#pragma unroll
        for (int i = 0; i < 4; i++) {
            float xn = sXn[ns * 4 + i];
            float4 kv;
            kv.x = __expf(fminf(fmaf(2.0f, s[i][0], -(xn + sqn[qs * 4 + 0])), 0.0f) * 0.0078125f);
            kv.y = __expf(fminf(fmaf(2.0f, s[i][1], -(xn + sqn[qs * 4 + 1])), 0.0f) * 0.0078125f);
            kv.z = __expf(fminf(fmaf(2.0f, s[i][2], -(xn + sqn[qs * 4 + 2])), 0.0f) * 0.0078125f);
            kv.w = __expf(fminf(fmaf(2.0f, s[i][3], -(xn + sqn[qs * 4 + 3])), 0.0f) * 0.0078125f);
            *reinterpret_cast<float4*>(&sK[(ns * 4 + i) * 68 + qs * 4]) = kv;
        }
        __syncthreads();

        // z phase: z[q][j] += K[n][q] * Lam[n][j]
#pragma unroll 4
        for (int n = 0; n < 64; n++) {
            float lam = sL[n * 36 + j];
            float4 k0 = *reinterpret_cast<const float4*>(&sK[n * 68 + qz * 8]);
            float4 k1 = *reinterpret_cast<const float4*>(&sK[n * 68 + qz * 8 + 4]);
            z[0] = fmaf(k0.x, lam, z[0]);
            z[1] = fmaf(k0.y, lam, z[1]);
            z[2] = fmaf(k0.z, lam, z[2]);
            z[3] = fmaf(k0.w, lam, z[3]);
            z[4] = fmaf(k1.x, lam, z[4]);
            z[5] = fmaf(k1.y, lam, z[5]);
            z[6] = fmaf(k1.z, lam, z[6]);
            z[7] = fmaf(k1.w, lam, z[7]);
        }
    }
#pragma unroll
    for (int i = 0; i < 8; i++)
        atomicAdd(&out[(q0 + qz * 8 + i) * 32 + j], z[i]);
}

// ---------------- launch ----------------
extern "C" void kernel_launch(void* const* d_in, const int* in_sizes, int n_in,
                              void* d_out, int out_size)
{
    const float* x_mu        = (const float*)d_in[0];
    const float* y_eta       = (const float*)d_in[1];
    const float* y_mean      = (const float*)d_in[2];
    const float* y_var       = (const float*)d_in[3];
    const float* X_mean      = (const float*)d_in[4];
    const float* X_var       = (const float*)d_in[5];
    const float* Z_mean      = (const float*)d_in[6];
    const float* Z_var       = (const float*)d_in[7];
    const float* kXXmean_inv = (const float*)d_in[8];
    const float* kXXvar_inv  = (const float*)d_in[9];
    float* out = (float*)d_out;

    const int SM64 = (2 * 64 * 68 + 64 * 68 + 64 * 36 + 128) * (int)sizeof(float);
    const int SM96 = (2 * 96 * 68 + 64 * 68 + 64 * 36 + 128) * (int)sizeof(float);
    cudaFuncSetAttribute(fused_rbf_kernel<64, 0>,
                         cudaFuncAttributeMaxDynamicSharedMemorySize, SM64);
    cudaFuncSetAttribute(fused_rbf_kernel<96, 1>,
                         cudaFuncAttributeMaxDynamicSharedMemorySize, SM96);

    zero_L_kernel<<<256, 256>>>();
    build_queries_kernel<<<256, 256>>>(x_mu, y_eta, y_mean, y_var, out);
    transpose_norm_kernel<64, 0><<<256, 256>>>(X_mean);
    transpose_norm_kernel<96, 1><<<256, 256>>>(X_var);

    lambda_gemm_kernel<0><<<dim3(32, 8), 256>>>(kXXmean_inv, Z_mean);
    lambda_gemm_kernel<1><<<dim3(32, 8), 256>>>(kXXvar_inv, Z_var);

    fused_rbf_kernel<64, 0><<<dim3(128, 2), 256, SM64>>>(out);
    fused_rbf_kernel<96, 1><<<dim3(128, 2), 256, SM96>>>(out);
}

// round 3
// speedup vs baseline: 1.0014x; 1.0014x over previous
#include <cuda_runtime.h>
#include <cstdint>

#define N 8192

// ---------------- device scratch (no allocations allowed) ----------------
__device__ float g_xmT[64 * N];   // built query features, transposed [64][N]
__device__ float g_xvT[96 * N];   // [96][N]
__device__ float g_XmT[64 * N];   // X_mean transposed
__device__ float g_XvT[96 * N];   // X_var transposed
__device__ float g_qn_mean[N];    // ||x_mean row||^2
__device__ float g_qn_var[N];
__device__ float g_Xn_mean[N];    // ||X_mean row||^2
__device__ float g_Xn_var[N];
__device__ float g_Lmean[N * 32]; // Lambda_mean
__device__ float g_Lvar[N * 32];  // Lambda_var

// ---------------- zero Lambda accumulators ----------------
__global__ void zero_L_kernel() {
    int i = blockIdx.x * blockDim.x + threadIdx.x;
    const int total = N * 32;
    for (; i < total; i += gridDim.x * blockDim.x) {
        g_Lmean[i] = 0.0f;
        g_Lvar[i]  = 0.0f;
    }
}

// ---------------- build query features (transposed) + norms + seed output ----------------
// x_mean = [x_mu, y_mean+y_var]            (64)
// x_var  = [x_mu, 0.01*flip(y_eta), y_mean+y_var] (96)
// out    = y_mean + y_var   (z terms added later via atomicAdd)
__global__ __launch_bounds__(256) void build_queries_kernel(
    const float* __restrict__ x_mu, const float* __restrict__ y_eta,
    const float* __restrict__ y_mean, const float* __restrict__ y_var,
    float* __restrict__ out)
{
    __shared__ float sa[32][33];
    __shared__ float se[32][33];
    __shared__ float ss[32][33];
    int q0   = blockIdx.x * 32;
    int tid  = threadIdx.x;
    int lane = tid & 31;
    int w    = tid >> 5;

#pragma unroll
    for (int rr = 0; rr < 4; rr++) {
        int qr = w + rr * 8;
        int q  = q0 + qr;
        float a = x_mu[q * 32 + lane];
        float s = y_mean[q * 32 + lane] + y_var[q * 32 + lane];
        float e = 0.01f * y_eta[(N - 1 - q) * 32 + lane];
        sa[qr][lane] = a;
        se[qr][lane] = e;
        ss[qr][lane] = s;
        out[q * 32 + lane] = s;
        float nm = a * a + s * s;
        float nv = nm + e * e;
#pragma unroll
        for (int o = 16; o > 0; o >>= 1) {
            nm += __shfl_xor_sync(0xffffffffu, nm, o);
            nv += __shfl_xor_sync(0xffffffffu, nv, o);
        }
        if (lane == 0) { g_qn_mean[q] = nm; g_qn_var[q] = nv; }
    }
    __syncthreads();
    // transposed writes: coalesced over q
    for (int idx = tid; idx < 64 * 32; idx += 256) {
        int k = idx >> 5, c = idx & 31;
        float v = (k < 32) ? sa[c][k] : ss[c][k - 32];
        g_xmT[k * N + q0 + c] = v;
    }
    for (int idx = tid; idx < 96 * 32; idx += 256) {
        int k = idx >> 5, c = idx & 31;
        float v = (k < 32) ? sa[c][k] : ((k < 64) ? se[c][k - 32] : ss[c][k - 64]);
        g_xvT[k * N + q0 + c] = v;
    }
}

// ---------------- transpose X + row norms ----------------
template <int D, int V>
__global__ __launch_bounds__(256) void transpose_norm_kernel(const float* __restrict__ X)
{
    float* XT = V ? g_XvT : g_XmT;
    float* n2 = V ? g_Xn_var : g_Xn_mean;
    __shared__ float s[32][D + 1];
    int q0  = blockIdx.x * 32;
    int tid = threadIdx.x;
    for (int idx = tid; idx < 32 * D; idx += 256) {
        int r = idx / D, c = idx - r * D;
        s[r][c] = X[(q0 + r) * D + c];
    }
    __syncthreads();
    if (tid < 32) {
        float acc = 0.0f;
#pragma unroll 8
        for (int k = 0; k < D; k++) { float v = s[tid][k]; acc = fmaf(v, v, acc); }
        n2[q0 + tid] = acc;
    }
    for (int idx = tid; idx < D * 32; idx += 256) {
        int k = idx >> 5, c = idx & 31;
        XT[k * N + q0 + c] = s[c][k];
    }
}

// ---------------- Lambda = kXX_inv @ Z   ([N][N] @ [N][32]) ----------------
// grid (32 row-blocks of 256 rows, 8 k-splits), block 256, thread tile 4 rows x 8 cols
template <int V>
__global__ __launch_bounds__(256) void lambda_gemm_kernel(
    const float* __restrict__ A, const float* __restrict__ B)
{
    float* C = V ? g_Lvar : g_Lmean;
    __shared__ float sA[256][20];
    __shared__ float sB[16][36];
    int tid   = threadIdx.x;
    int r0    = blockIdx.x * 256;
    int kbase = blockIdx.y * (N / 8);
    int tx = tid & 3;        // col group: 8 cols
    int ty = tid >> 2;       // 0..63: rows ty*4..+3

    float acc[4][8];
#pragma unroll
    for (int i = 0; i < 4; i++)
#pragma unroll
        for (int j = 0; j < 8; j++) acc[i][j] = 0.0f;

    for (int kc = kbase; kc < kbase + N / 8; kc += 16) {
#pragma unroll
        for (int i = 0; i < 4; i++) {
            int f   = tid + 256 * i;
            int row = f >> 2;
            int kq  = (f & 3) << 2;
            float4 v = *reinterpret_cast<const float4*>(&A[(size_t)(r0 + row) * N + kc + kq]);
            *reinterpret_cast<float4*>(&sA[row][kq]) = v;
        }
        if (tid < 128) {
            int k = tid >> 3, jq = (tid & 7) << 2;
            *reinterpret_cast<float4*>(&sB[k][jq]) =
                *reinterpret_cast<const float4*>(&B[(kc + k) * 32 + jq]);
        }
        __syncthreads();
#pragma unroll
        for (int k = 0; k < 16; k++) {
            float4 b0 = *reinterpret_cast<const float4*>(&sB[k][tx * 8]);
            float4 b1 = *reinterpret_cast<const float4*>(&sB[k][tx * 8 + 4]);
#pragma unroll
            for (int i = 0; i < 4; i++) {
                float a = sA[ty * 4 + i][k];
                acc[i][0] = fmaf(a, b0.x, acc[i][0]);
                acc[i][1] = fmaf(a, b0.y, acc[i][1]);
                acc[i][2] = fmaf(a, b0.z, acc[i][2]);
                acc[i][3] = fmaf(a, b0.w, acc[i][3]);
                acc[i][4] = fmaf(a, b1.x, acc[i][4]);
                acc[i][5] = fmaf(a, b1.y, acc[i][5]);
                acc[i][6] = fmaf(a, b1.z, acc[i][6]);
                acc[i][7] = fmaf(a, b1.w, acc[i][7]);
            }
        }
        __syncthreads();
    }
#pragma unroll
    for (int i = 0; i < 4; i++)
#pragma unroll
        for (int j = 0; j < 8; j++)
            atomicAdd(&C[(size_t)(r0 + ty * 4 + i) * 32 + tx * 8 + j], acc[i][j]);
}

// ---------------- fused RBF + z gemm ----------------
// z[q][:] += sum_n exp(min(2*dot - ||X_n||^2 - ||x_q||^2, 0)/128) * Lambda[n][:]
// grid (128 q-tiles of 64, 2 n-splits of 4096), block 256
template <int D, int V>
__global__ __launch_bounds__(256) void fused_rbf_kernel(float* __restrict__ out)
{
    const float* XT  = V ? g_XvT     : g_XmT;
    const float* qT  = V ? g_xvT     : g_xmT;
    const float* Xn2 = V ? g_Xn_var  : g_Xn_mean;
    const float* qn2 = V ? g_qn_var  : g_qn_mean;
    const float* Lam = V ? g_Lvar    : g_Lmean;

    extern __shared__ float sm[];
    float* sq  = sm;              // [D][68]
    float* sX  = sq + D * 68;     // [D][68]
    float* sK  = sX + D * 68;     // [64][68]
    float* sL  = sK + 64 * 68;    // [64][36]
    float* sXn = sL + 64 * 36;    // [64]
    float* sqn = sXn + 64;        // [64]

    int tid    = threadIdx.x;
    int q0     = blockIdx.x * 64;
    int n0base = blockIdx.y * (N / 2);

    for (int idx = tid; idx < D * 64; idx += 256) {
        int k = idx >> 6, c = idx & 63;
        sq[k * 68 + c] = qT[k * N + q0 + c];
    }
    if (tid < 64) sqn[tid] = qn2[q0 + tid];

    float z[8];
#pragma unroll
    for (int i = 0; i < 8; i++) z[i] = 0.0f;

    int qs = tid >> 4;   // 0..15 (S-phase q group of 4)
    int ns = tid & 15;   // 0..15 (S-phase n group of 4)
    int qz = tid >> 5;   // 0..7  (z-phase q group of 8)
    int j  = tid & 31;   // z-phase output column

    for (int n0 = n0base; n0 < n0base + N / 2; n0 += 64) {
        __syncthreads();
        for (int idx = tid; idx < D * 64; idx += 256) {
            int k = idx >> 6, c = idx & 63;
            sX[k * 68 + c] = XT[k * N + n0 + c];
        }
        for (int idx = tid; idx < 512; idx += 256) {
            int n = idx >> 3, jq = (idx & 7) << 2;
            *reinterpret_cast<float4*>(&sL[n * 36 + jq]) =
                *reinterpret_cast<const float4*>(&Lam[(n0 + n) * 32 + jq]);
        }
        if (tid < 64) sXn[tid] = Xn2[n0 + tid];
        __syncthreads();

        // S phase: 4x4 dots
        float s[4][4];
#pragma unroll
        for (int i = 0; i < 4; i++)
#pragma unroll
            for (int jj = 0; jj < 4; jj++) s[i][jj] = 0.0f;

#pragma unroll 4
        for (int k = 0; k < D; k++) {
            float4 xa = *reinterpret_cast<const float4*>(&sX[k * 68 + ns * 4]);
            float4 qa = *reinterpret_cast<const float4*>(&sq[k * 68 + qs * 4]);
            float xv[4] = {xa.x, xa.y, xa.z, xa.w};
            float qv[4] = {qa.x, qa.y, qa.z, qa.w};
#pragma unroll
            for (int i = 0; i < 4; i++)
#pragma unroll
                for (int jj = 0; jj < 4; jj++)
                    s[i][jj] = fmaf(xv[i], qv[jj], s[i][jj]);
        }
        // exp + write K tile
#pragma unroll
        for (int i = 0; i < 4; i++) {
            float xn = sXn[ns * 4 + i];
            float4 kv;
            kv.x = __expf(fminf(fmaf(2.0f, s[i][0], -(xn + sqn[qs * 4 + 0])), 0.0f) * 0.0078125f);
            kv.y = __expf(fminf(fmaf(2.0f, s[i][1], -(xn + sqn[qs * 4 + 1])), 0.0f) * 0.0078125f);
            kv.z = __expf(fminf(fmaf(2.0f, s[i][2], -(xn + sqn[qs * 4 + 2])), 0.0f) * 0.0078125f);
            kv.w = __expf(fminf(fmaf(2.0f, s[i][3], -(xn + sqn[qs * 4 + 3])), 0.0f) * 0.0078125f);
            *reinterpret_cast<float4*>(&sK[(ns * 4 + i) * 68 + qs * 4]) = kv;
        }
        __syncthreads();

        // z phase: z[q][j] += K[n][q] * Lam[n][j]
#pragma unroll 4
        for (int n = 0; n < 64; n++) {
            float lam = sL[n * 36 + j];
            float4 k0 = *reinterpret_cast<const float4*>(&sK[n * 68 + qz * 8]);
            float4 k1 = *reinterpret_cast<const float4*>(&sK[n * 68 + qz * 8 + 4]);
            z[0] = fmaf(k0.x, lam, z[0]);
            z[1] = fmaf(k0.y, lam, z[1]);
            z[2] = fmaf(k0.z, lam, z[2]);
            z[3] = fmaf(k0.w, lam, z[3]);
            z[4] = fmaf(k1.x, lam, z[4]);
            z[5] = fmaf(k1.y, lam, z[5]);
            z[6] = fmaf(k1.z, lam, z[6]);
            z[7] = fmaf(k1.w, lam, z[7]);
        }
    }
#pragma unroll
    for (int i = 0; i < 8; i++)
        atomicAdd(&out[(q0 + qz * 8 + i) * 32 + j], z[i]);
}

// ---------------- launch ----------------
extern "C" void kernel_launch(void* const* d_in, const int* in_sizes, int n_in,
                              void* d_out, int out_size)
{
    const float* x_mu        = (const float*)d_in[0];
    const float* y_eta       = (const float*)d_in[1];
    const float* y_mean      = (const float*)d_in[2];
    const float* y_var       = (const float*)d_in[3];
    const float* X_mean      = (const float*)d_in[4];
    const float* X_var       = (const float*)d_in[5];
    const float* Z_mean      = (const float*)d_in[6];
    const float* Z_var       = (const float*)d_in[7];
    const float* kXXmean_inv = (const float*)d_in[8];
    const float* kXXvar_inv  = (const float*)d_in[9];
    float* out = (float*)d_out;

    const int SM64 = (2 * 64 * 68 + 64 * 68 + 64 * 36 + 128) * (int)sizeof(float);
    const int SM96 = (2 * 96 * 68 + 64 * 68 + 64 * 36 + 128) * (int)sizeof(float);
    cudaFuncSetAttribute(fused_rbf_kernel<64, 0>,
                         cudaFuncAttributeMaxDynamicSharedMemorySize, SM64);
    cudaFuncSetAttribute(fused_rbf_kernel<96, 1>,
                         cudaFuncAttributeMaxDynamicSharedMemorySize, SM96);

    zero_L_kernel<<<256, 256>>>();
    build_queries_kernel<<<256, 256>>>(x_mu, y_eta, y_mean, y_var, out);
    transpose_norm_kernel<64, 0><<<256, 256>>>(X_mean);
    transpose_norm_kernel<96, 1><<<256, 256>>>(X_var);

    lambda_gemm_kernel<0><<<dim3(32, 8), 256>>>(kXXmean_inv, Z_mean);
    lambda_gemm_kernel<1><<<dim3(32, 8), 256>>>(kXXvar_inv, Z_var);

    fused_rbf_kernel<64, 0><<<dim3(128, 2), 256, SM64>>>(out);
    fused_rbf_kernel<96, 1><<<dim3(128, 2), 256, SM96>>>(out);
}